// round 1
// baseline (speedup 1.0000x reference)
#include <cuda_runtime.h>
#include <cuda_bf16.h>

// Exact Euclidean distance transform (matches scipy distance_transform_edt /
// the Meijster two-phase reference) on a 1536x1536 binary mask.
//
// Strategy: fused per-row kernel with outward-expanding windowed searches.
//   Phase 1 (vertical, per pixel): g[i][j] = distance to nearest background
//     pixel in column j. Expand t = 0,1,2,... checking rows i-t and i+t;
//     the first hit is the minimum, so break immediately. If no background
//     exists in the column, g = BIG = R + C (reference's cap).
//   Phase 2 (horizontal, per pixel): d2[j] = min_k g2[k] + (j-k)^2, restricted
//     to |j-k| = t with t^2 < best-so-far (candidates with t^2 >= best cannot
//     improve since g2 >= 0). Expanding t outward from 0 keeps this exact.
//
// For a random ~50% background mask both loops terminate after ~2-4 steps,
// making the whole transform effectively O(R*C) and memory-bound.
//
// All values involved (g^2 <= 3072^2, t^2 <= 1535^2, sums < 2^24) are exactly
// representable in fp32, so results match the reference bit-for-bit up to the
// final sqrt rounding.

#define R_DIM 1536
#define C_DIM 1536
#define BIG_I (R_DIM + C_DIM)

__global__ __launch_bounds__(256) void edt_kernel(
    const float* __restrict__ mask, float* __restrict__ out)
{
    const int row = blockIdx.x;
    const int tid = threadIdx.x;

    __shared__ float g2s[C_DIM];

    // ---- phase 1: vertical windowed nearest-background search ----
    #pragma unroll 1
    for (int j = tid; j < C_DIM; j += 256) {
        int best = BIG_I;
        #pragma unroll 1
        for (int t = 0; t < R_DIM; ++t) {
            const int up = row - t;
            const int dn = row + t;
            bool hit = false;
            if (up >= 0    && mask[up * C_DIM + j] == 0.0f) hit = true;
            if (dn < R_DIM && mask[dn * C_DIM + j] == 0.0f) hit = true;
            if (hit) { best = t; break; }
        }
        const float g = (float)best;
        g2s[j] = g * g;
    }

    __syncthreads();

    // ---- phase 2: horizontal windowed min-plus ----
    #pragma unroll 1
    for (int j = tid; j < C_DIM; j += 256) {
        float best = g2s[j];  // t = 0 candidate
        #pragma unroll 1
        for (int t = 1; t < C_DIM; ++t) {
            const float t2 = (float)(t * t);
            if (t2 >= best) break;  // no farther candidate can improve
            const int l = j - t;
            const int r = j + t;
            if (l >= 0)     best = fminf(best, g2s[l] + t2);
            if (r < C_DIM)  best = fminf(best, g2s[r] + t2);
        }
        out[row * C_DIM + j] = sqrtf(best);
    }
}

extern "C" void kernel_launch(void* const* d_in, const int* in_sizes, int n_in,
                              void* d_out, int out_size) {
    const float* mask = (const float*)d_in[0];
    float* out = (float*)d_out;
    edt_kernel<<<R_DIM, 256>>>(mask, out);
}

// round 2
// speedup vs baseline: 1.3933x; 1.3933x over previous
#include <cuda_runtime.h>
#include <cuda_bf16.h>
#include <stdint.h>

// Exact Euclidean distance transform (matches the Meijster-style reference)
// on a 1536x1536 binary mask.
//
// Two kernels:
//   1) pack_kernel: build a column-packed background bitmap.
//      colbits[w*C + j] bit b  ==  (mask[(w*32+b)*C + j] == 0)
//      288 KB total -> fully L2-resident, coalesced across j.
//   2) edt_kernel (one block per row):
//      phase 1: vertical nearest-background via ffs/clz on bitmap words.
//               For a random mask this resolves in the FIRST word load
//               (covers +/-31 rows), with an exact outward word expansion
//               for rare far cases. Cap 3072 (= R+C) when column is all-fg.
//      phase 2: horizontal min-plus with exact early-exit window
//               (t^2 >= best cannot improve since g2 >= 0), from shared mem.
//
// All quantities (g^2 <= 3072^2 < 2^24, t^2, sums) are integers exactly
// representable in fp32 -> bit-exact up to final sqrt rounding.

#define R_DIM 1536
#define C_DIM 1536
#define W_DIM (R_DIM / 32)   // 48 words per column
#define BIG_I (R_DIM + C_DIM)

__device__ uint32_t g_colbits[W_DIM * C_DIM];

__global__ __launch_bounds__(1024) void pack_kernel(const float* __restrict__ mask)
{
    __shared__ uint32_t sh[32][33];
    const int tx = threadIdx.x, ty = threadIdx.y;
    const int col  = blockIdx.x * 32 + tx;
    const int rowg = blockIdx.y * 32 + ty;

    // coalesced load of a 32x32 tile; sh[row_in_tile][col_in_tile]
    sh[ty][tx] = (mask[rowg * C_DIM + col] == 0.0f) ? 1u : 0u;
    __syncthreads();

    // warp ty reads column (blockIdx.x*32 + ty): lane tx supplies row bit tx
    const uint32_t word = __ballot_sync(0xffffffffu, sh[tx][ty] != 0u);
    if (tx == 0)
        g_colbits[blockIdx.y * C_DIM + blockIdx.x * 32 + ty] = word;
}

__global__ __launch_bounds__(256) void edt_kernel(float* __restrict__ out)
{
    const int row = blockIdx.x;
    const int tid = threadIdx.x;
    const int wi  = row >> 5;
    const int bi  = row & 31;

    __shared__ float g2s[C_DIM];

    // ---- phase 1: vertical nearest background via bitmap ----
    #pragma unroll 1
    for (int j = tid; j < C_DIM; j += 256) {
        const uint32_t w = g_colbits[wi * C_DIM + j];
        int best = BIG_I;

        const uint32_t md = w >> bi;          // bit 0 == this row, going down
        if (md) best = __ffs(md) - 1;
        const uint32_t mu = w << (31 - bi);   // bit 31 == this row, going up
        if (mu) best = min(best, __clz(mu));

        // exact outward expansion over neighboring words (rare path)
        int wd = wi + 1, dn_off = 32 - bi;    // t of bit0 in word wd
        int wu = wi - 1, up_off = bi + 1;     // t of bit31 in word wu
        while ((wd < W_DIM && dn_off < best) || (wu >= 0 && up_off < best)) {
            if (wd < W_DIM && dn_off < best) {
                const uint32_t x = g_colbits[wd * C_DIM + j];
                if (x) best = min(best, dn_off + __ffs(x) - 1);
                ++wd; dn_off += 32;
            } else wd = W_DIM;
            if (wu >= 0 && up_off < best) {
                const uint32_t x = g_colbits[wu * C_DIM + j];
                if (x) best = min(best, up_off + __clz(x));
                --wu; up_off += 32;
            } else wu = -1;
        }

        const float g = (float)best;
        g2s[j] = g * g;
    }

    __syncthreads();

    // ---- phase 2: horizontal windowed min-plus (exact early exit) ----
    #pragma unroll 1
    for (int j = tid; j < C_DIM; j += 256) {
        float best = g2s[j];
        #pragma unroll 1
        for (int t = 1; t < C_DIM; ++t) {
            const float t2 = (float)(t * t);
            if (t2 >= best) break;
            const int l = j - t;
            const int r = j + t;
            if (l >= 0)     best = fminf(best, g2s[l] + t2);
            if (r < C_DIM)  best = fminf(best, g2s[r] + t2);
        }
        out[row * C_DIM + j] = sqrtf(best);
    }
}

extern "C" void kernel_launch(void* const* d_in, const int* in_sizes, int n_in,
                              void* d_out, int out_size) {
    const float* mask = (const float*)d_in[0];
    float* out = (float*)d_out;

    dim3 pgrid(C_DIM / 32, R_DIM / 32);
    dim3 pblock(32, 32);
    pack_kernel<<<pgrid, pblock>>>(mask);
    edt_kernel<<<R_DIM, 256>>>(out);
}

// round 3
// speedup vs baseline: 1.9698x; 1.4138x over previous
#include <cuda_runtime.h>
#include <cuda_bf16.h>
#include <stdint.h>

// Exact Euclidean distance transform (matches the Meijster-style reference)
// on a 1536x1536 binary mask.
//
// Kernel 1 (pack): column-packed background bitmap via warp ballot transpose.
//   colbits[w*C + j] bit b  ==  (mask[(w*32+b)*C + j] == 0).  288 KB, L2-resident.
//   One warp per 32x32 tile: 32 coalesced row loads + 32 ballots, each lane
//   assembles its own column's word. No shared memory, no syncthreads.
//
// Kernel 2 (edt, one block of 512 per row):
//   phase 1: vertical nearest-background via ffs/clz on bitmap words
//            (3 words per thread loaded up-front for MLP), exact outward
//            word expansion for rare far cases, cap 3072 (= R+C).
//   phase 2: horizontal min-plus with exact early-exit window
//            (candidates with t^2 >= best cannot improve since g2 >= 0).
//
// All quantities (g^2 <= 3072^2 < 2^24, t^2, sums) are integers exactly
// representable in fp32 -> bit-exact up to final sqrt rounding.

#define R_DIM 1536
#define C_DIM 1536
#define W_DIM (R_DIM / 32)     // 48 words per column
#define BIG_I (R_DIM + C_DIM)
#define EDT_T 512              // threads per edt block
#define JPT   (C_DIM / EDT_T)  // 3 columns per thread

__device__ uint32_t g_colbits[W_DIM * C_DIM];

// 8 warps/block, each warp packs one 32x32 tile.
__global__ __launch_bounds__(256) void pack_kernel(const float* __restrict__ mask)
{
    const int lane = threadIdx.x & 31;
    const int warp = threadIdx.x >> 5;
    const int col0 = (blockIdx.x * 8 + warp) * 32;
    const int row0 = blockIdx.y * 32;

    const float* p = mask + row0 * C_DIM + col0 + lane;

    uint32_t myword = 0;
    #pragma unroll
    for (int r = 0; r < 32; ++r) {
        const uint32_t b = __ballot_sync(0xffffffffu, p[r * C_DIM] == 0.0f);
        myword |= ((b >> lane) & 1u) << r;
    }
    g_colbits[blockIdx.y * C_DIM + col0 + lane] = myword;
}

__global__ __launch_bounds__(EDT_T) void edt_kernel(float* __restrict__ out)
{
    const int row = blockIdx.x;
    const int tid = threadIdx.x;
    const int wi  = row >> 5;
    const int bi  = row & 31;

    __shared__ float g2s[C_DIM];

    // ---- phase 1: vertical nearest background via bitmap ----
    uint32_t w[JPT];
    #pragma unroll
    for (int u = 0; u < JPT; ++u)
        w[u] = g_colbits[wi * C_DIM + tid + u * EDT_T];   // batched: MLP=JPT

    #pragma unroll
    for (int u = 0; u < JPT; ++u) {
        const int j = tid + u * EDT_T;
        int best = BIG_I;

        const uint32_t md = w[u] >> bi;          // bit 0 == this row, downward
        if (md) best = __ffs(md) - 1;
        const uint32_t mu = w[u] << (31 - bi);   // bit 31 == this row, upward
        if (mu) best = min(best, __clz(mu));

        // exact outward expansion over neighboring words (rare path)
        int wd = wi + 1, dn_off = 32 - bi;
        int wu = wi - 1, up_off = bi + 1;
        while ((wd < W_DIM && dn_off < best) || (wu >= 0 && up_off < best)) {
            if (wd < W_DIM && dn_off < best) {
                const uint32_t x = g_colbits[wd * C_DIM + j];
                if (x) best = min(best, dn_off + __ffs(x) - 1);
                ++wd; dn_off += 32;
            } else wd = W_DIM;
            if (wu >= 0 && up_off < best) {
                const uint32_t x = g_colbits[wu * C_DIM + j];
                if (x) best = min(best, up_off + __clz(x));
                --wu; up_off += 32;
            } else wu = -1;
        }

        const float g = (float)best;
        g2s[j] = g * g;
    }

    __syncthreads();

    // ---- phase 2: horizontal windowed min-plus (exact early exit) ----
    #pragma unroll
    for (int u = 0; u < JPT; ++u) {
        const int j = tid + u * EDT_T;
        float best = g2s[j];
        #pragma unroll 1
        for (int t = 1; t < C_DIM; ++t) {
            const float t2 = (float)(t * t);
            if (t2 >= best) break;
            const int l = j - t;
            const int r = j + t;
            if (l >= 0)     best = fminf(best, g2s[l] + t2);
            if (r < C_DIM)  best = fminf(best, g2s[r] + t2);
        }
        out[row * C_DIM + j] = sqrtf(best);
    }
}

extern "C" void kernel_launch(void* const* d_in, const int* in_sizes, int n_in,
                              void* d_out, int out_size) {
    const float* mask = (const float*)d_in[0];
    float* out = (float*)d_out;

    dim3 pgrid(C_DIM / 256, R_DIM / 32);   // 6 x 48 blocks, 8 warps each
    pack_kernel<<<pgrid, 256>>>(mask);
    edt_kernel<<<R_DIM, EDT_T>>>(out);
}